// round 1
// baseline (speedup 1.0000x reference)
#include <cuda_runtime.h>

#define NN 100000
#define NE 1600000
#define NBLK ((NN + 255) / 256)   // 391 blocks of 256 over nodes

// ---------------- static device scratch (allocation-free) ----------------
__device__ int   g_cnt[NN];
__device__ int   g_rowptr[NN + 1];
__device__ int   g_cursor[NN];
__device__ int   g_colidx[NE];
__device__ float g_deginv[NN];
__device__ float g_Y[(size_t)NN * 128];   // GEMM output: [N, 2*fout] (ys | yn)
__device__ float g_H[(size_t)NN * 64];    // hidden activations (pre-BN)
__device__ float g_s1[64];
__device__ float g_s2[64];
__device__ float g_aff[128];              // a[0..64), c[64..128)
__device__ int   g_bsum[512];
__device__ int   g_boff[512];

// ---------------- CSR build ----------------
__global__ void k_init() {
    int i = blockIdx.x * 256 + threadIdx.x;
    if (i < NN) g_cnt[i] = 0;
    if (i < 64) { g_s1[i] = 0.f; g_s2[i] = 0.f; }
}

__global__ void k_hist(const int* __restrict__ dst) {
    int e = blockIdx.x * 256 + threadIdx.x;
    if (e < NE) atomicAdd(&g_cnt[dst[e]], 1);
}

__global__ void k_scan_block() {
    __shared__ int sh[256];
    int i = blockIdx.x * 256 + threadIdx.x;
    int v = (i < NN) ? g_cnt[i] : 0;
    sh[threadIdx.x] = v;
    __syncthreads();
    #pragma unroll
    for (int off = 1; off < 256; off <<= 1) {
        int t = (threadIdx.x >= off) ? sh[threadIdx.x - off] : 0;
        __syncthreads();
        sh[threadIdx.x] += t;
        __syncthreads();
    }
    if (i < NN) g_rowptr[i] = sh[threadIdx.x] - v;   // block-local exclusive
    if (threadIdx.x == 255) g_bsum[blockIdx.x] = sh[255];
}

__global__ void k_scan_tops(int nb) {
    __shared__ int sh[512];
    int t = threadIdx.x;
    int v = (t < nb) ? g_bsum[t] : 0;
    sh[t] = v;
    __syncthreads();
    #pragma unroll
    for (int off = 1; off < 512; off <<= 1) {
        int tt = (t >= off) ? sh[t - off] : 0;
        __syncthreads();
        sh[t] += tt;
        __syncthreads();
    }
    g_boff[t] = sh[t] - v;   // exclusive
}

__global__ void k_scan_add() {
    int i = blockIdx.x * 256 + threadIdx.x;
    if (i < NN) {
        int rp = g_rowptr[i] + g_boff[blockIdx.x];
        g_rowptr[i] = rp;
        g_cursor[i] = rp;
        int c = g_cnt[i];
        g_deginv[i] = 1.0f / (float)(c > 1 ? c : 1);
    }
    if (blockIdx.x == 0 && threadIdx.x == 0) g_rowptr[NN] = NE;
}

__global__ void k_fill(const int* __restrict__ src, const int* __restrict__ dst) {
    int e = blockIdx.x * 256 + threadIdx.x;
    if (e < NE) {
        int d = dst[e];
        int p = atomicAdd(&g_cursor[d], 1);
        g_colidx[p] = src[e];
    }
}

// ---------------- fused GEMM: C[M, NC] = A[M,K] @ [Ws | Wn], with optional
// input transform (BN affine of previous layer, optional ReLU) --------------
template <int K, int NC, int BM, int TM, int TN, int NT, bool AFF, bool RELU>
__global__ __launch_bounds__(NT) void k_gemm(
    const float* __restrict__ A,
    const float* __restrict__ Ws, const float* __restrict__ Wn,
    float* __restrict__ C, int M)
{
    constexpr int BK = 16;
    constexpr int F  = NC / 2;
    constexpr int CG = NC / TN;
    __shared__ __align__(16) float Wt[BK][NC];
    __shared__ __align__(16) float At[BK][BM + 4];

    const int tid = threadIdx.x;
    const int tx  = tid % CG;
    const int ty  = tid / CG;
    const int row0 = blockIdx.x * BM;

    float acc[TM][TN];
    #pragma unroll
    for (int i = 0; i < TM; i++)
        #pragma unroll
        for (int j = 0; j < TN; j++) acc[i][j] = 0.f;

    for (int k0 = 0; k0 < K; k0 += BK) {
        // load weight tile (Ws cols [0,F), Wn cols [F,NC))
        #pragma unroll
        for (int idx = tid; idx < BK * NC; idx += NT) {
            int kk = idx / NC, c = idx % NC;
            int kg = k0 + kk;
            Wt[kk][c] = (c < F) ? Ws[kg * F + c] : Wn[kg * F + (c - F)];
        }
        // load A tile (transposed to [k][row]) with optional BN affine + relu
        #pragma unroll
        for (int idx = tid; idx < BM * BK; idx += NT) {
            int r = idx / BK, kk = idx % BK;
            int row = row0 + r, kg = k0 + kk;
            float v = (row < M) ? A[(size_t)row * K + kg] : 0.f;
            if (AFF) {
                v = fmaf(v, g_aff[kg], g_aff[64 + kg]);
                if (RELU) v = fmaxf(v, 0.f);
            }
            At[kk][r] = v;
        }
        __syncthreads();
        #pragma unroll
        for (int kk = 0; kk < BK; kk++) {
            float a[TM], b[TN];
            #pragma unroll
            for (int i = 0; i < TM; i++) a[i] = At[kk][ty * TM + i];
            #pragma unroll
            for (int j = 0; j < TN; j++) b[j] = Wt[kk][tx * TN + j];
            #pragma unroll
            for (int i = 0; i < TM; i++)
                #pragma unroll
                for (int j = 0; j < TN; j++)
                    acc[i][j] = fmaf(a[i], b[j], acc[i][j]);
        }
        __syncthreads();
    }

    #pragma unroll
    for (int i = 0; i < TM; i++) {
        int row = row0 + ty * TM + i;
        if (row < M) {
            #pragma unroll
            for (int j = 0; j < TN; j += 4) {
                float4 v = make_float4(acc[i][j], acc[i][j + 1],
                                       acc[i][j + 2], acc[i][j + 3]);
                *(float4*)(C + (size_t)row * NC + tx * TN + j) = v;
            }
        }
    }
}

// ---------------- CSR mean-aggregation + self + bias + BN stats (F=64) -----
// warp per node; lane owns 2 feature columns (float2 gathers are coalesced,
// working set is L2-resident).
__global__ void k_agg64(const float* __restrict__ Y, const float* __restrict__ bias,
                        float* __restrict__ H, int M)
{
    __shared__ float ss[128];   // [0,64): sum, [64,128): sumsq
    int tid = threadIdx.x;
    if (tid < 128) ss[tid] = 0.f;
    __syncthreads();

    int lane = tid & 31, w = tid >> 5;
    int c0 = lane * 2;
    float bx = bias[c0], by = bias[c0 + 1];
    float p1 = 0.f, p2 = 0.f, q1 = 0.f, q2 = 0.f;

    for (int v = blockIdx.x * 8 + w; v < M; v += gridDim.x * 8) {
        int beg = g_rowptr[v], end = g_rowptr[v + 1];
        float ax = 0.f, ay = 0.f;
        for (int e = beg; e < end; e++) {
            int s = g_colidx[e];
            float2 t = *(const float2*)(Y + (size_t)s * 128 + 64 + c0);
            ax += t.x;
            ay += t.y;
        }
        float di = g_deginv[v];
        float2 ys = *(const float2*)(Y + (size_t)v * 128 + c0);
        float hx = fmaf(ax, di, ys.x) + bx;
        float hy = fmaf(ay, di, ys.y) + by;
        float2 hv; hv.x = hx; hv.y = hy;
        *(float2*)(H + (size_t)v * 64 + c0) = hv;
        p1 += hx; p2 += hx * hx;
        q1 += hy; q2 += hy * hy;
    }
    atomicAdd(&ss[c0], p1);      atomicAdd(&ss[64 + c0], p2);
    atomicAdd(&ss[c0 + 1], q1);  atomicAdd(&ss[64 + c0 + 1], q2);
    __syncthreads();
    if (tid < 64) {
        atomicAdd(&g_s1[tid], ss[tid]);
        atomicAdd(&g_s2[tid], ss[64 + tid]);
    }
}

// ---------------- final layer aggregation (F=16, Y stride 32, no BN) -------
__global__ void k_agg16(const float* __restrict__ Y, const float* __restrict__ bias,
                        float* __restrict__ O, int M)
{
    int tid = threadIdx.x, lane = tid & 31, w = tid >> 5;
    bool act = lane < 16;
    float b = act ? bias[lane] : 0.f;
    for (int v = blockIdx.x * 8 + w; v < M; v += gridDim.x * 8) {
        int beg = g_rowptr[v], end = g_rowptr[v + 1];
        float a = 0.f;
        for (int e = beg; e < end; e++) {
            int s = g_colidx[e];
            if (act) a += Y[(size_t)s * 32 + 16 + lane];
        }
        if (act) {
            float ys = Y[(size_t)v * 32 + lane];
            O[(size_t)v * 16 + lane] = fmaf(a, g_deginv[v], ys) + b;
        }
    }
}

// ---------------- BN finalize: build affine for next layer's GEMM loads ----
__global__ void k_bnfinal(const float* __restrict__ g, const float* __restrict__ be,
                          float invN)
{
    int t = threadIdx.x;   // 64 threads
    float m   = g_s1[t] * invN;
    float var = g_s2[t] * invN - m * m;
    float r   = rsqrtf(var + 1e-5f);
    float a   = r * g[t];
    g_aff[t]      = a;
    g_aff[64 + t] = fmaf(-m, a, be[t]);
    g_s1[t] = 0.f;
    g_s2[t] = 0.f;
}

// ---------------- launch ----------------
extern "C" void kernel_launch(void* const* d_in, const int* in_sizes, int n_in,
                              void* d_out, int out_size)
{
    const float* x   = (const float*)d_in[0];
    const int*   src = (const int*)d_in[1];
    const int*   dst = (const int*)d_in[2];
    const float* Ws1 = (const float*)d_in[3];
    const float* Wn1 = (const float*)d_in[4];
    const float* b1  = (const float*)d_in[5];
    const float* g1  = (const float*)d_in[6];
    const float* be1 = (const float*)d_in[7];
    const float* Ws2 = (const float*)d_in[8];
    const float* Wn2 = (const float*)d_in[9];
    const float* b2  = (const float*)d_in[10];
    const float* g2  = (const float*)d_in[11];
    const float* be2 = (const float*)d_in[12];
    const float* Ws3 = (const float*)d_in[13];
    const float* Wn3 = (const float*)d_in[14];
    const float* b3  = (const float*)d_in[15];
    const float* g3  = (const float*)d_in[16];
    const float* be3 = (const float*)d_in[17];
    const float* Ws4 = (const float*)d_in[18];
    const float* Wn4 = (const float*)d_in[19];
    const float* b4  = (const float*)d_in[20];
    float* out = (float*)d_out;

    float *Yp, *Hp;
    cudaGetSymbolAddress((void**)&Yp, g_Y);
    cudaGetSymbolAddress((void**)&Hp, g_H);

    const int EB = (NE + 255) / 256;
    const int GB = (NN + 127) / 128;     // GEMM row blocks (782)
    const int AGG_GRID = 1184;           // 8 warps/block, grid-stride over nodes
    const float invN = 1.0f / (float)NN;

    // build CSC (dst-grouped) once per launch
    k_init<<<NBLK, 256>>>();
    k_hist<<<EB, 256>>>(dst);
    k_scan_block<<<NBLK, 256>>>();
    k_scan_tops<<<1, 512>>>(NBLK);
    k_scan_add<<<NBLK, 256>>>();
    k_fill<<<EB, 256>>>(src, dst);

    // layer 1: SAGE(128->64) + BN (affine deferred to layer-2 GEMM loads)
    k_gemm<128, 128, 128, 8, 8, 256, false, false><<<GB, 256>>>(x, Ws1, Wn1, Yp, NN);
    k_agg64<<<AGG_GRID, 256>>>(Yp, b1, Hp, NN);
    k_bnfinal<<<1, 64>>>(g1, be1, invN);

    // layer 2: SAGE(64->64) + BN + (ReLU deferred); input = BN1(h1), no relu
    k_gemm<64, 128, 128, 8, 8, 256, true, false><<<GB, 256>>>(Hp, Ws2, Wn2, Yp, NN);
    k_agg64<<<AGG_GRID, 256>>>(Yp, b2, Hp, NN);
    k_bnfinal<<<1, 64>>>(g2, be2, invN);

    // layer 3: input = relu(BN2(h2))
    k_gemm<64, 128, 128, 8, 8, 256, true, true><<<GB, 256>>>(Hp, Ws3, Wn3, Yp, NN);
    k_agg64<<<AGG_GRID, 256>>>(Yp, b3, Hp, NN);
    k_bnfinal<<<1, 64>>>(g3, be3, invN);

    // layer 4: SAGE(64->16), input = relu(BN3(h3)), output straight to d_out
    k_gemm<64, 32, 128, 8, 4, 128, true, true><<<GB, 128>>>(Hp, Ws4, Wn4, Yp, NN);
    k_agg16<<<AGG_GRID, 256>>>(Yp, b4, out, NN);
}